// round 12
// baseline (speedup 1.0000x reference)
#include <cuda_runtime.h>
#include <cuda_fp16.h>
#include <mma.h>
#include <cstdint>

using namespace nvcuda;

#define BATCH 64
#define TT    256
#define HHH   1024
#define GGG   4096
#define MTOT  (BATCH*TT)   // 16384

#define NBLK  64           // recurrence blocks
#define GR    64           // gate rows per block
#define NTHR  256
#define WLD   1032         // weight smem row stride (half), mult of 8
#define CHUNK 256
#define ALD   264          // A-tile smem row stride (half), mult of 8
#define ABUF  (64*ALD)     // halfs per A buffer (16896)

// Dynamic smem: sW 64*1032*2 + sA 2*16896*2 + sg 64*68*4 + sbias 64*4
#define SMEM_TOTAL (132096 + 67584 + 17408 + 256)   // 217344

// ----------------------------------------------------------------------------
// Device-global scratch (allocation-free)
// ----------------------------------------------------------------------------
__device__ __align__(16) half  g_wih[3][GGG*HHH];
__device__ __align__(16) half  g_whh[3][GGG*HHH];
__device__            float g_bias[3][GGG];
__device__ __align__(16) float g_xg[(size_t)MTOT*GGG];    // permuted gate cols
__device__ __align__(16) half  g_in[(size_t)MTOT*HHH];    // layer input (layers 1,2)
__device__ __align__(16) half  g_h[2][BATCH*HHH];         // double-buffered hidden
__device__            float g_hlast[BATCH*HHH];           // final h of last layer
__device__            unsigned g_bar;                     // grid barrier counter (monotonic)

// Gate-row permutation: permuted row cp -> original row of [4H, K] weight.
// 32-row perm block p <-> (gate = (cp&31)>>3, h = 8*(cp>>5) + (cp&7)).
__device__ __forceinline__ int perm_row(int cp) {
    int pb = cp >> 5, r = cp & 31;
    return (r >> 3) * HHH + pb * 8 + (r & 7);
}

__device__ __forceinline__ float fsig(float x) {
    return 1.f / (1.f + __expf(-x));
}
__device__ __forceinline__ float ftanh(float x) {
    return 1.f - 2.f / (__expf(2.f * x) + 1.f);
}

// ----------------------------------------------------------------------------
// Prep: both weight matrices of one layer in one launch
// ----------------------------------------------------------------------------
__global__ void prep_w_both(const float* __restrict__ wih,
                            const float* __restrict__ whh, int l, int K) {
    size_t idx = (size_t)blockIdx.x * blockDim.x + threadIdx.x;
    size_t n1 = (size_t)GGG * K;
    size_t n2 = (size_t)GGG * HHH;
    if (idx < n1) {
        int rp = (int)(idx / K), c = (int)(idx % K);
        g_wih[l][idx] = __float2half(wih[(size_t)perm_row(rp) * K + c]);
    } else if (idx < n1 + n2) {
        size_t j = idx - n1;
        int rp = (int)(j / HHH), c = (int)(j % HHH);
        g_whh[l][j] = __float2half(whh[(size_t)perm_row(rp) * HHH + c]);
    }
}

// All biases (3 layers), h-state init, barrier counter init — one launch.
__global__ void prep_misc(const float* __restrict__ bi0, const float* __restrict__ bh0,
                          const float* __restrict__ bi1, const float* __restrict__ bh1,
                          const float* __restrict__ bi2, const float* __restrict__ bh2) {
    int i = blockIdx.x * blockDim.x + threadIdx.x;     // 65536 threads
    g_h[0][i] = __float2half(0.f);
    if (i < 3 * GGG) {
        int l = i >> 12, cp = i & (GGG - 1);
        int r = perm_row(cp);
        const float* bi = (l == 0) ? bi0 : (l == 1) ? bi1 : bi2;
        const float* bh = (l == 0) ? bh0 : (l == 1) ? bh1 : bh2;
        g_bias[l][cp] = bi[r] + bh[r];
    }
    if (i == 0) g_bar = 0u;
}

// ----------------------------------------------------------------------------
// xg GEMM: g_xg[M,4096] = A[M,K](fp16) @ B[4096,K]^T(fp16), fp32 accum.
// Block tile 128x128, 8 warps (2x4), warp tile 64x32, k-chunk 32, reg-staged DB.
// Layer 0 reads fp32 x directly and converts on the fly.
// ----------------------------------------------------------------------------
__global__ void __launch_bounds__(256) xg_gemm_kernel(int l, int K,
                                                      const float* __restrict__ xsrc) {
    __shared__ __align__(32) half sA[2][128][40], sB[2][128][40];
    int m0 = blockIdx.y * 128, n0 = blockIdx.x * 128;
    int tid = threadIdx.x, warp = tid >> 5;
    int wm = warp >> 2, wn = warp & 3;
    bool f32src = (l == 0);

    wmma::fragment<wmma::accumulator, 16, 16, 16, float> acc[4][2];
#pragma unroll
    for (int i = 0; i < 4; i++)
#pragma unroll
        for (int j = 0; j < 2; j++) wmma::fill_fragment(acc[i][j], 0.f);

    const half* B = g_wih[l];
    int r = tid >> 1, c16 = (tid & 1) * 16;
    uint4 ra[2], rb[2];

#define LOAD_A(k0)                                                             \
    do {                                                                       \
        if (f32src) {                                                          \
            const float* p = xsrc + (size_t)(m0 + r) * K + (k0) + c16;         \
            float4 f0 = *(const float4*)(p + 0);                               \
            float4 f1 = *(const float4*)(p + 4);                               \
            float4 f2 = *(const float4*)(p + 8);                               \
            float4 f3 = *(const float4*)(p + 12);                              \
            __half2 h0 = __floats2half2_rn(f0.x, f0.y);                        \
            __half2 h1 = __floats2half2_rn(f0.z, f0.w);                        \
            __half2 h2 = __floats2half2_rn(f1.x, f1.y);                        \
            __half2 h3 = __floats2half2_rn(f1.z, f1.w);                        \
            __half2 h4 = __floats2half2_rn(f2.x, f2.y);                        \
            __half2 h5 = __floats2half2_rn(f2.z, f2.w);                        \
            __half2 h6 = __floats2half2_rn(f3.x, f3.y);                        \
            __half2 h7 = __floats2half2_rn(f3.z, f3.w);                        \
            ra[0] = make_uint4(*(unsigned*)&h0, *(unsigned*)&h1,               \
                               *(unsigned*)&h2, *(unsigned*)&h3);              \
            ra[1] = make_uint4(*(unsigned*)&h4, *(unsigned*)&h5,               \
                               *(unsigned*)&h6, *(unsigned*)&h7);              \
        } else {                                                               \
            const half* p = g_in + (size_t)(m0 + r) * K + (k0) + c16;          \
            ra[0] = *(const uint4*)p;                                          \
            ra[1] = *(const uint4*)(p + 8);                                    \
        }                                                                      \
    } while (0)

#define LOAD_B(k0)                                                             \
    do {                                                                       \
        const half* p = B + (size_t)(n0 + r) * K + (k0) + c16;                 \
        rb[0] = *(const uint4*)p;                                              \
        rb[1] = *(const uint4*)(p + 8);                                        \
    } while (0)

#define STS(buf)                                                               \
    do {                                                                       \
        *(uint4*)&sA[buf][r][c16]     = ra[0];                                 \
        *(uint4*)&sA[buf][r][c16 + 8] = ra[1];                                 \
        *(uint4*)&sB[buf][r][c16]     = rb[0];                                 \
        *(uint4*)&sB[buf][r][c16 + 8] = rb[1];                                 \
    } while (0)

    int nch = K / 32;
    LOAD_A(0); LOAD_B(0);
    STS(0);
    __syncthreads();

    for (int ch = 0; ch < nch; ch++) {
        int cur = ch & 1;
        if (ch + 1 < nch) { LOAD_A((ch + 1) * 32); LOAD_B((ch + 1) * 32); }
#pragma unroll
        for (int ks = 0; ks < 2; ks++) {
            wmma::fragment<wmma::matrix_a, 16, 16, 16, half, wmma::row_major> af[4];
            wmma::fragment<wmma::matrix_b, 16, 16, 16, half, wmma::col_major> bf[2];
#pragma unroll
            for (int i = 0; i < 4; i++)
                wmma::load_matrix_sync(af[i], &sA[cur][wm * 64 + i * 16][ks * 16], 40);
#pragma unroll
            for (int j = 0; j < 2; j++)
                wmma::load_matrix_sync(bf[j], &sB[cur][wn * 32 + j * 16][ks * 16], 40);
#pragma unroll
            for (int i = 0; i < 4; i++)
#pragma unroll
                for (int j = 0; j < 2; j++)
                    wmma::mma_sync(acc[i][j], af[i], bf[j], acc[i][j]);
        }
        if (ch + 1 < nch) STS(cur ^ 1);
        __syncthreads();
    }
#undef LOAD_A
#undef LOAD_B
#undef STS

#pragma unroll
    for (int i = 0; i < 4; i++)
#pragma unroll
        for (int j = 0; j < 2; j++) {
            size_t row = (size_t)(m0 + wm * 64 + i * 16);
            int col = n0 + wn * 32 + j * 16;
            wmma::store_matrix_sync(&g_xg[row * GGG + col], acc[i][j], GGG,
                                    wmma::mem_row_major);
        }
}

// ----------------------------------------------------------------------------
// Persistent recurrence: 64 blocks, block nb owns gate rows [64nb,64nb+64)
// => h slice [16nb,16nb+16). Whh slice (132KB) in smem for all 256 steps.
// k-loop: 4 double-buffered chunks of 256 (reg-staged). 4 accumulator chains.
// Monotonic epoch grid barrier; h-state zeroed at t=255 for the next layer.
// ----------------------------------------------------------------------------
__global__ void __launch_bounds__(NTHR, 1) layer_kernel(int l) {
    extern __shared__ __align__(16) char smem_raw[];
    half*  sW    = (half*)smem_raw;               // [64][WLD]
    half*  sA    = sW + 64 * WLD;                 // [2][64][ALD]
    float* sg    = (float*)(sA + 2 * ABUF);       // [64][68]
    float* sbias = sg + 64 * 68;                  // [64]

    int nb = blockIdx.x;
    int tid = threadIdx.x, warp = tid >> 5;
    int wm = warp >> 1, wn = warp & 1;            // 4x2 warps over 64x64 tile

    // --- Load Whh slice (64 rows x 1024) into smem once ---
    {
        const half* Bw = &g_whh[l][(size_t)(nb * GR) * HHH];
        for (int i = tid; i < 64 * 128; i += NTHR) {       // 128 uint4/row
            int r = i >> 7, c = (i & 127) * 8;
            *(uint4*)&sW[r * WLD + c] = *(const uint4*)&Bw[(size_t)r * HHH + c];
        }
        if (tid < 64) sbias[tid] = g_bias[l][nb * GR + tid];
    }
    __syncthreads();

    int bq = tid >> 2;                 // batch row 0..63
    int hh2 = (tid & 3) * 2;           // 0,2,4,6
    float c0a = 0.f, c0b = 0.f, c1a = 0.f, c1b = 0.f;   // cell state (2 sub-blocks x 2 lanes)
    unsigned bbase = (unsigned)l * 255u * NBLK;

    wmma::fragment<wmma::accumulator, 16, 16, 16, float> acc[2][2];
    uint4 ra[8];

    for (int t = 0; t < TT; t++) {
        int rp = t & 1, wp = rp ^ 1;
        const half* Ah = g_h[rp];

        // Prefetch xg values (latency hidden by k-loop)
        size_t xbase = ((size_t)bq * TT + t) * GGG + nb * GR;
        float2 x0 = *(const float2*)&g_xg[xbase + hh2];
        float2 x1 = *(const float2*)&g_xg[xbase + 8 + hh2];
        float2 x2 = *(const float2*)&g_xg[xbase + 16 + hh2];
        float2 x3 = *(const float2*)&g_xg[xbase + 24 + hh2];
        float2 y0 = *(const float2*)&g_xg[xbase + 32 + hh2];
        float2 y1 = *(const float2*)&g_xg[xbase + 40 + hh2];
        float2 y2 = *(const float2*)&g_xg[xbase + 48 + hh2];
        float2 y3 = *(const float2*)&g_xg[xbase + 56 + hh2];

#pragma unroll
        for (int j = 0; j < 2; j++)
#pragma unroll
            for (int p = 0; p < 2; p++) wmma::fill_fragment(acc[j][p], 0.f);

        // Prologue: chunk 0 -> buf 0 (64 rows x 256 halfs = 2048 uint4)
#pragma unroll
        for (int u = 0; u < 8; u++) {
            int idx = tid + u * NTHR;
            int r = idx >> 5, c = (idx & 31) * 8;
            *(uint4*)&sA[0 * ABUF + r * ALD + c] = *(const uint4*)&Ah[(size_t)r * HHH + c];
        }
        __syncthreads();

        for (int ch = 0; ch < 4; ch++) {
            int cur = ch & 1;
            if (ch < 3) {
                int k0n = (ch + 1) * CHUNK;
#pragma unroll
                for (int u = 0; u < 8; u++) {
                    int idx = tid + u * NTHR;
                    int r = idx >> 5, c = (idx & 31) * 8;
                    ra[u] = *(const uint4*)&Ah[(size_t)r * HHH + k0n + c];
                }
            }
            const half* bufA = sA + cur * ABUF;
#pragma unroll
            for (int ks = 0; ks < 16; ks++) {
                wmma::fragment<wmma::matrix_a, 16, 16, 16, half, wmma::row_major> af;
                wmma::fragment<wmma::matrix_b, 16, 16, 16, half, wmma::col_major> bf0, bf1;
                wmma::load_matrix_sync(af, &bufA[(wm * 16) * ALD + ks * 16], ALD);
                wmma::load_matrix_sync(bf0, &sW[(wn * 32) * WLD + ch * CHUNK + ks * 16], WLD);
                wmma::load_matrix_sync(bf1, &sW[(wn * 32 + 16) * WLD + ch * CHUNK + ks * 16], WLD);
                int p = ks & 1;
                wmma::mma_sync(acc[0][p], af, bf0, acc[0][p]);
                wmma::mma_sync(acc[1][p], af, bf1, acc[1][p]);
            }
            if (ch < 3) {
#pragma unroll
                for (int u = 0; u < 8; u++) {
                    int idx = tid + u * NTHR;
                    int r = idx >> 5, c = (idx & 31) * 8;
                    *(uint4*)&sA[(cur ^ 1) * ABUF + r * ALD + c] = ra[u];
                }
            }
            __syncthreads();
        }

        // Merge parity chains, stage gates [64 x 64] to smem
#pragma unroll
        for (int j = 0; j < 2; j++) {
#pragma unroll
            for (int e = 0; e < acc[j][0].num_elements; e++) acc[j][0].x[e] += acc[j][1].x[e];
            wmma::store_matrix_sync(&sg[(wm * 16) * 68 + wn * 32 + j * 16], acc[j][0],
                                    68, wmma::mem_row_major);
        }
        __syncthreads();

        // Fused LSTM cell update: 2 sub-blocks x 2 lanes per thread
        {
            const float* row = &sg[bq * 68];
            bool last = (t == TT - 1);

            // sub-block 0 (gate cols 0..31, h = 16nb + hh2)
            float iv0 = row[hh2]          + x0.x + sbias[hh2];
            float iv1 = row[hh2 + 1]      + x0.y + sbias[hh2 + 1];
            float fv0 = row[8 + hh2]      + x1.x + sbias[8 + hh2];
            float fv1 = row[8 + hh2 + 1]  + x1.y + sbias[8 + hh2 + 1];
            float gv0 = row[16 + hh2]     + x2.x + sbias[16 + hh2];
            float gv1 = row[16 + hh2 + 1] + x2.y + sbias[16 + hh2 + 1];
            float ov0 = row[24 + hh2]     + x3.x + sbias[24 + hh2];
            float ov1 = row[24 + hh2 + 1] + x3.y + sbias[24 + hh2 + 1];
            c0a = fsig(fv0) * c0a + fsig(iv0) * ftanh(gv0);
            c0b = fsig(fv1) * c0b + fsig(iv1) * ftanh(gv1);
            float h00 = fsig(ov0) * ftanh(c0a);
            float h01 = fsig(ov1) * ftanh(c0b);

            // sub-block 1 (gate cols 32..63, h = 16nb + 8 + hh2)
            float jv0 = row[32 + hh2]     + y0.x + sbias[32 + hh2];
            float jv1 = row[32 + hh2 + 1] + y0.y + sbias[32 + hh2 + 1];
            float kv0 = row[40 + hh2]     + y1.x + sbias[40 + hh2];
            float kv1 = row[40 + hh2 + 1] + y1.y + sbias[40 + hh2 + 1];
            float lv0 = row[48 + hh2]     + y2.x + sbias[48 + hh2];
            float lv1 = row[48 + hh2 + 1] + y2.y + sbias[48 + hh2 + 1];
            float mv0 = row[56 + hh2]     + y3.x + sbias[56 + hh2];
            float mv1 = row[56 + hh2 + 1] + y3.y + sbias[56 + hh2 + 1];
            c1a = fsig(kv0) * c1a + fsig(jv0) * ftanh(lv0);
            c1b = fsig(kv1) * c1b + fsig(jv1) * ftanh(lv1);
            float h10 = fsig(mv0) * ftanh(c1a);
            float h11 = fsig(mv1) * ftanh(c1b);

            int hidx0 = nb * 16 + hh2;
            int hidx1 = nb * 16 + 8 + hh2;
            __half2 p0, p1, z2;
            p0.x = __float2half(h00); p0.y = __float2half(h01);
            p1.x = __float2half(h10); p1.y = __float2half(h11);
            z2.x = __float2half(0.f); z2.y = __float2half(0.f);

            // at t=255: zero g_h[wp] (==g_h[0]) so next layer starts clean
            *(__half2*)&g_h[wp][bq * HHH + hidx0] = last ? z2 : p0;
            *(__half2*)&g_h[wp][bq * HHH + hidx1] = last ? z2 : p1;
            if (l < 2) {
                size_t m = (size_t)bq * TT + t;
                *(__half2*)&g_in[m * HHH + hidx0] = p0;
                *(__half2*)&g_in[m * HHH + hidx1] = p1;
            }
            if (l == 2 && last) {
                g_hlast[bq * HHH + hidx0]     = h00;
                g_hlast[bq * HHH + hidx0 + 1] = h01;
                g_hlast[bq * HHH + hidx1]     = h10;
                g_hlast[bq * HHH + hidx1 + 1] = h11;
            }
        }

        // Epoch grid barrier (monotonic counter; skip after last step)
        if (t < TT - 1) {
            __threadfence();
            __syncthreads();
            if (tid == 0) {
                atomicAdd(&g_bar, 1u);
                unsigned want = bbase + (unsigned)(t + 1) * NBLK;
                volatile unsigned* p = &g_bar;
                while (*p < want) { }
                __threadfence();
            }
            __syncthreads();
        }
    }
}

// ----------------------------------------------------------------------------
// Final FC: out[b] = hlast[b, :] . fc_w + fc_b   (D_OUT = 1)
// ----------------------------------------------------------------------------
__global__ void fc_kernel(const float* __restrict__ fw, const float* __restrict__ fb,
                          float* __restrict__ out) {
    int b = blockIdx.x, tid = threadIdx.x;
    __shared__ float red[256];
    const float* hrow = &g_hlast[b * HHH];
    float s = 0.f;
    for (int h = tid; h < HHH; h += 256) s += hrow[h] * fw[h];
    red[tid] = s;
    __syncthreads();
    for (int off = 128; off; off >>= 1) {
        if (tid < off) red[tid] += red[tid + off];
        __syncthreads();
    }
    if (tid == 0) out[b] = red[0] + fb[0];
}

// ----------------------------------------------------------------------------
// Launch (my index 3 == layer_kernel(l0) -> ncu capture slot)
// ----------------------------------------------------------------------------
extern "C" void kernel_launch(void* const* d_in, const int* in_sizes, int n_in,
                              void* d_out, int out_size) {
    const float* x = (const float*)d_in[0];

    cudaFuncSetAttribute(layer_kernel, cudaFuncAttributeMaxDynamicSharedMemorySize,
                         SMEM_TOTAL);

    // ---- layer 0 ----
    {
        size_t tot = (size_t)GGG * 256 + (size_t)GGG * HHH;
        prep_w_both<<<(unsigned)((tot + 255) / 256), 256>>>(
            (const float*)d_in[1], (const float*)d_in[2], 0, 256);
        prep_misc<<<256, 256>>>(
            (const float*)d_in[3], (const float*)d_in[4],
            (const float*)d_in[7], (const float*)d_in[8],
            (const float*)d_in[11], (const float*)d_in[12]);
        dim3 grid(GGG / 128, MTOT / 128);
        xg_gemm_kernel<<<grid, 256>>>(0, 256, x);
        layer_kernel<<<NBLK, NTHR, SMEM_TOTAL>>>(0);
    }
    // ---- layers 1,2 ----
    for (int l = 1; l < 3; l++) {
        size_t tot = (size_t)GGG * HHH * 2;
        prep_w_both<<<(unsigned)((tot + 255) / 256), 256>>>(
            (const float*)d_in[1 + 4 * l], (const float*)d_in[2 + 4 * l], l, 1024);
        dim3 grid(GGG / 128, MTOT / 128);
        xg_gemm_kernel<<<grid, 256>>>(l, 1024, x);
        layer_kernel<<<NBLK, NTHR, SMEM_TOTAL>>>(l);
    }
    fc_kernel<<<BATCH, 256>>>((const float*)d_in[13], (const float*)d_in[14],
                              (float*)d_out);
}

// round 13
// speedup vs baseline: 1.1486x; 1.1486x over previous
#include <cuda_runtime.h>
#include <cuda_fp16.h>
#include <mma.h>
#include <cstdint>

using namespace nvcuda;

#define BATCH 64
#define TT    256
#define HHH   1024
#define GGG   4096
#define MTOT  (BATCH*TT)   // 16384

#define NBLK  128
#define NTHR  256
#define GR    32           // gate rows (perm) per block
#define RLD   1032         // resident weight smem row stride (halfs)
#define SLD   72           // streamed tile smem row stride (halfs)
#define ABUF  (64*SLD)     // 4608 halfs per A buffer
#define BBUF  (32*SLD)     // 2304 halfs per B buffer
#define NSTEP 258          // wavefront steps: t0=s, t1=s-1, t2=s-2

// smem: sWres 2*32*1032*2 =132096 | sA 2*4608*2 =18432 | sB0+sB1 2*(2*2304*2)=18432
//       sg 64*36*4 =9216 | sbias 96*4 =384   => 178560
#define SMEM_TOTAL (132096 + 18432 + 18432 + 9216 + 384)

// ----------------------------------------------------------------------------
// Device-global scratch (allocation-free)
// ----------------------------------------------------------------------------
__device__ __align__(16) half  g_wih[3][GGG*HHH];   // [0]: only first GGG*256 used
__device__ __align__(16) half  g_whh[3][GGG*HHH];
__device__            float g_bias[3][GGG];
__device__ __align__(16) float g_xg[(size_t)MTOT*GGG];   // layer-0 input gates only
__device__ __align__(16) half  g_hst[3][2][BATCH*HHH];   // per-layer double-buffered h
__device__            float g_hlast[BATCH*HHH];
__device__            unsigned g_bar;

__device__ __forceinline__ int perm_row(int cp) {
    int pb = cp >> 5, r = cp & 31;
    return (r >> 3) * HHH + pb * 8 + (r & 7);
}
__device__ __forceinline__ float fsig(float x)  { return 1.f / (1.f + __expf(-x)); }
__device__ __forceinline__ float ftanh(float x) { return 1.f - 2.f / (__expf(2.f * x) + 1.f); }

// ----------------------------------------------------------------------------
// Prep: all 6 weight matrices, one launch
// ----------------------------------------------------------------------------
__global__ void prep_all(const float* __restrict__ wih0, const float* __restrict__ whh0,
                         const float* __restrict__ wih1, const float* __restrict__ whh1,
                         const float* __restrict__ wih2, const float* __restrict__ whh2) {
    size_t idx = (size_t)blockIdx.x * blockDim.x + threadIdx.x;
    const size_t N0 = (size_t)GGG * 256, NB = (size_t)GGG * HHH;
    if (idx >= N0 + 5 * NB) return;
    if (idx < N0) {
        int rp = (int)(idx / 256), c = (int)(idx % 256);
        g_wih[0][idx] = __float2half(wih0[(size_t)perm_row(rp) * 256 + c]);
        return;
    }
    idx -= N0;
    int region = (int)(idx / NB);
    size_t j = idx % NB;
    int rp = (int)(j / HHH), c = (int)(j % HHH);
    size_t src = (size_t)perm_row(rp) * HHH + c;
    switch (region) {
        case 0: g_whh[0][j] = __float2half(whh0[src]); break;
        case 1: g_wih[1][j] = __float2half(wih1[src]); break;
        case 2: g_whh[1][j] = __float2half(whh1[src]); break;
        case 3: g_wih[2][j] = __float2half(wih2[src]); break;
        default: g_whh[2][j] = __float2half(whh2[src]); break;
    }
}

// Biases, h-state zero (both parities, 3 layers), barrier counter
__global__ void prep_misc(const float* __restrict__ bi0, const float* __restrict__ bh0,
                          const float* __restrict__ bi1, const float* __restrict__ bh1,
                          const float* __restrict__ bi2, const float* __restrict__ bh2) {
    int i = blockIdx.x * blockDim.x + threadIdx.x;     // 65536 threads
    half z = __float2half(0.f);
#pragma unroll
    for (int l = 0; l < 3; l++) {
        g_hst[l][0][i] = z;
        g_hst[l][1][i] = z;
    }
    if (i < 3 * GGG) {
        int l = i >> 12, cp = i & (GGG - 1);
        int r = perm_row(cp);
        const float* bi = (l == 0) ? bi0 : (l == 1) ? bi1 : bi2;
        const float* bh = (l == 0) ? bh0 : (l == 1) ? bh1 : bh2;
        g_bias[l][cp] = bi[r] + bh[r];
    }
    if (i == 0) g_bar = 0u;
}

// ----------------------------------------------------------------------------
// xg GEMM (layer 0 only): g_xg[16384,4096] = x[16384,256](fp32->fp16) @ Wih0^T
// ----------------------------------------------------------------------------
__global__ void __launch_bounds__(256) xg_gemm_kernel(const float* __restrict__ xsrc) {
    const int K = 256;
    __shared__ __align__(32) half sA[2][128][40], sB[2][128][40];
    int m0 = blockIdx.y * 128, n0 = blockIdx.x * 128;
    int tid = threadIdx.x, warp = tid >> 5;
    int wm = warp >> 2, wn = warp & 3;

    wmma::fragment<wmma::accumulator, 16, 16, 16, float> acc[4][2];
#pragma unroll
    for (int i = 0; i < 4; i++)
#pragma unroll
        for (int j = 0; j < 2; j++) wmma::fill_fragment(acc[i][j], 0.f);

    const half* B = g_wih[0];
    int r = tid >> 1, c16 = (tid & 1) * 16;
    uint4 ra[2], rb[2];

#define LOAD_A(k0)                                                             \
    do {                                                                       \
        const float* p = xsrc + (size_t)(m0 + r) * K + (k0) + c16;             \
        float4 f0 = *(const float4*)(p + 0);                                   \
        float4 f1 = *(const float4*)(p + 4);                                   \
        float4 f2 = *(const float4*)(p + 8);                                   \
        float4 f3 = *(const float4*)(p + 12);                                  \
        __half2 h0 = __floats2half2_rn(f0.x, f0.y);                            \
        __half2 h1 = __floats2half2_rn(f0.z, f0.w);                            \
        __half2 h2 = __floats2half2_rn(f1.x, f1.y);                            \
        __half2 h3 = __floats2half2_rn(f1.z, f1.w);                            \
        __half2 h4 = __floats2half2_rn(f2.x, f2.y);                            \
        __half2 h5 = __floats2half2_rn(f2.z, f2.w);                            \
        __half2 h6 = __floats2half2_rn(f3.x, f3.y);                            \
        __half2 h7 = __floats2half2_rn(f3.z, f3.w);                            \
        ra[0] = make_uint4(*(unsigned*)&h0, *(unsigned*)&h1,                   \
                           *(unsigned*)&h2, *(unsigned*)&h3);                  \
        ra[1] = make_uint4(*(unsigned*)&h4, *(unsigned*)&h5,                   \
                           *(unsigned*)&h6, *(unsigned*)&h7);                  \
    } while (0)
#define LOAD_B(k0)                                                             \
    do {                                                                       \
        const half* p = B + (size_t)(n0 + r) * K + (k0) + c16;                 \
        rb[0] = *(const uint4*)p;                                              \
        rb[1] = *(const uint4*)(p + 8);                                        \
    } while (0)
#define STS(buf)                                                               \
    do {                                                                       \
        *(uint4*)&sA[buf][r][c16]     = ra[0];                                 \
        *(uint4*)&sA[buf][r][c16 + 8] = ra[1];                                 \
        *(uint4*)&sB[buf][r][c16]     = rb[0];                                 \
        *(uint4*)&sB[buf][r][c16 + 8] = rb[1];                                 \
    } while (0)

    int nch = K / 32;
    LOAD_A(0); LOAD_B(0);
    STS(0);
    __syncthreads();
    for (int ch = 0; ch < nch; ch++) {
        int cur = ch & 1;
        if (ch + 1 < nch) { LOAD_A((ch + 1) * 32); LOAD_B((ch + 1) * 32); }
#pragma unroll
        for (int ks = 0; ks < 2; ks++) {
            wmma::fragment<wmma::matrix_a, 16, 16, 16, half, wmma::row_major> af[4];
            wmma::fragment<wmma::matrix_b, 16, 16, 16, half, wmma::col_major> bf[2];
#pragma unroll
            for (int i = 0; i < 4; i++)
                wmma::load_matrix_sync(af[i], &sA[cur][wm * 64 + i * 16][ks * 16], 40);
#pragma unroll
            for (int j = 0; j < 2; j++)
                wmma::load_matrix_sync(bf[j], &sB[cur][wn * 32 + j * 16][ks * 16], 40);
#pragma unroll
            for (int i = 0; i < 4; i++)
#pragma unroll
                for (int j = 0; j < 2; j++)
                    wmma::mma_sync(acc[i][j], af[i], bf[j], acc[i][j]);
        }
        if (ch + 1 < nch) STS(cur ^ 1);
        __syncthreads();
    }
#undef LOAD_A
#undef LOAD_B
#undef STS
#pragma unroll
    for (int i = 0; i < 4; i++)
#pragma unroll
        for (int j = 0; j < 2; j++) {
            size_t row = (size_t)(m0 + wm * 64 + i * 16);
            int col = n0 + wn * 32 + j * 16;
            wmma::store_matrix_sync(&g_xg[row * GGG + col], acc[i][j], GGG,
                                    wmma::mem_row_major);
        }
}

// ----------------------------------------------------------------------------
// Fused 3-layer wavefront recurrence. 128 co-resident blocks; block nb owns
// perm gate rows [32nb,32nb+32) (h slice [8nb,8nb+8)) of ALL layers.
// Step s: L0@t=s, L1@t=s-1, L2@t=s-2. Whh1/Whh2 smem-resident; Whh0/Wih1/Wih2
// streamed from L2. 3 A-passes/step, shared between layer pairs.
// ----------------------------------------------------------------------------
__global__ void __launch_bounds__(NTHR, 1) fused_lstm_kernel() {
    extern __shared__ __align__(16) char raw[];
    half*  sWres = (half*)raw;                  // [2][32][RLD]  (Whh1, Whh2)
    half*  sA    = sWres + 2 * 32 * RLD;        // [2][64][SLD]
    half*  sB0   = sA + 2 * ABUF;               // [2][32][SLD]
    half*  sB1   = sB0 + 2 * BBUF;              // [2][32][SLD]
    float* sg    = (float*)(sB1 + 2 * BBUF);    // [64][36]
    float* sbias = sg + 64 * 36;                // [3][32]

    int nb = blockIdx.x;
    int tid = threadIdx.x, warp = tid >> 5;
    int wm = warp >> 1, wn = warp & 1;          // 4x2 warps over 64x32 tile

    // Resident Whh1, Whh2 slices (32 rows x 1024 each)
    for (int i = tid; i < 2 * 32 * 128; i += NTHR) {
        int l = i >> 12;                         // 0..1
        int j = i & 4095;
        int r = j >> 7, c = (j & 127) * 8;
        *(uint4*)&sWres[l * 32 * RLD + r * RLD + c] =
            *(const uint4*)&g_whh[l + 1][(size_t)(nb * GR + r) * HHH + c];
    }
    if (tid < 96) { int l = tid >> 5, g = tid & 31; sbias[tid] = g_bias[l][nb * GR + g]; }
    __syncthreads();

    int bq = tid >> 2;                 // batch row 0..63
    int hh2 = (tid & 3) * 2;           // 0,2,4,6
    float c0a = 0.f, c0b = 0.f, c1a = 0.f, c1b = 0.f, c2a = 0.f, c2b = 0.f;

    const half* wS0 = &g_whh[0][(size_t)(nb * GR) * HHH];   // streamed Whh0
    const half* wS1 = &g_wih[1][(size_t)(nb * GR) * HHH];   // streamed Wih1
    const half* wS2 = &g_wih[2][(size_t)(nb * GR) * HHH];   // streamed Wih2

    int arw = tid >> 2, acl = (tid & 3) * 16;   // A tile 64x64: 2 uint4/thread
    int brw = tid >> 3, bcl = (tid & 7) * 8;    // B tile 32x64: 1 uint4/thread

    auto ldA = [&](const half* base, int k0, uint4& r0, uint4& r1) {
        const half* p = base + (size_t)arw * HHH + k0 + acl;
        r0 = *(const uint4*)p; r1 = *(const uint4*)(p + 8);
    };
    auto stA = [&](int buf, uint4 r0, uint4 r1) {
        *(uint4*)&sA[buf * ABUF + arw * SLD + acl]     = r0;
        *(uint4*)&sA[buf * ABUF + arw * SLD + acl + 8] = r1;
    };
    auto ldB = [&](const half* base, int k0, uint4& r0) {
        r0 = *(const uint4*)(base + (size_t)brw * HHH + k0 + bcl);
    };
    auto stB = [&](half* sBx, int buf, uint4 r0) {
        *(uint4*)&sBx[buf * BBUF + brw * SLD + bcl] = r0;
    };

    wmma::fragment<wmma::accumulator, 16, 16, 16, float> aG0, aG1, aG2;

    for (int s = 0; s < NSTEP; s++) {
        int rp = (s + 1) & 1, wp = s & 1;
        bool v0 = (s < 256), v1 = (s >= 1 && s < 257), v2 = (s >= 2);

        // L0 xg prefetch (latency hidden by pass loops)
        float2 x0, x1, x2, x3;
        if (v0) {
            size_t xb = ((size_t)bq * TT + s) * GGG + nb * GR;
            x0 = *(const float2*)&g_xg[xb + hh2];
            x1 = *(const float2*)&g_xg[xb + 8 + hh2];
            x2 = *(const float2*)&g_xg[xb + 16 + hh2];
            x3 = *(const float2*)&g_xg[xb + 24 + hh2];
        }

        wmma::fill_fragment(aG0, 0.f);
        wmma::fill_fragment(aG1, 0.f);
        wmma::fill_fragment(aG2, 0.f);

        uint4 a0, a1, b0, b1;

        // ---- Pass 1: A = h0(prev). B streams: Whh0 -> aG0, Wih1 -> aG1 ----
        {
            const half* hA = g_hst[0][rp];
            ldA(hA, 0, a0, a1); ldB(wS0, 0, b0); ldB(wS1, 0, b1);
            stA(0, a0, a1); stB(sB0, 0, b0); stB(sB1, 0, b1);
            __syncthreads();
            for (int ch = 0; ch < 16; ch++) {
                int cur = ch & 1;
                if (ch < 15) {
                    int k0 = (ch + 1) * 64;
                    ldA(hA, k0, a0, a1); ldB(wS0, k0, b0); ldB(wS1, k0, b1);
                }
#pragma unroll
                for (int ks = 0; ks < 4; ks++) {
                    wmma::fragment<wmma::matrix_a, 16, 16, 16, half, wmma::row_major> af;
                    wmma::fragment<wmma::matrix_b, 16, 16, 16, half, wmma::col_major> f0, f1;
                    wmma::load_matrix_sync(af, &sA[cur * ABUF + (wm * 16) * SLD + ks * 16], SLD);
                    wmma::load_matrix_sync(f0, &sB0[cur * BBUF + (wn * 16) * SLD + ks * 16], SLD);
                    wmma::load_matrix_sync(f1, &sB1[cur * BBUF + (wn * 16) * SLD + ks * 16], SLD);
                    wmma::mma_sync(aG0, af, f0, aG0);
                    wmma::mma_sync(aG1, af, f1, aG1);
                }
                if (ch < 15) { stA(cur ^ 1, a0, a1); stB(sB0, cur ^ 1, b0); stB(sB1, cur ^ 1, b1); }
                __syncthreads();
            }
        }

        // ---- Pass 2: A = h1(prev). Stream Wih2 -> aG2; resident Whh1 -> aG1 ----
        {
            const half* hA = g_hst[1][rp];
            ldA(hA, 0, a0, a1); ldB(wS2, 0, b0);
            stA(0, a0, a1); stB(sB0, 0, b0);
            __syncthreads();
            for (int ch = 0; ch < 16; ch++) {
                int cur = ch & 1;
                if (ch < 15) {
                    int k0 = (ch + 1) * 64;
                    ldA(hA, k0, a0, a1); ldB(wS2, k0, b0);
                }
#pragma unroll
                for (int ks = 0; ks < 4; ks++) {
                    wmma::fragment<wmma::matrix_a, 16, 16, 16, half, wmma::row_major> af;
                    wmma::fragment<wmma::matrix_b, 16, 16, 16, half, wmma::col_major> f0, f1;
                    wmma::load_matrix_sync(af, &sA[cur * ABUF + (wm * 16) * SLD + ks * 16], SLD);
                    wmma::load_matrix_sync(f0, &sB0[cur * BBUF + (wn * 16) * SLD + ks * 16], SLD);
                    wmma::load_matrix_sync(f1, &sWres[0 * 32 * RLD + (wn * 16) * RLD + ch * 64 + ks * 16], RLD);
                    wmma::mma_sync(aG2, af, f0, aG2);
                    wmma::mma_sync(aG1, af, f1, aG1);
                }
                if (ch < 15) { stA(cur ^ 1, a0, a1); stB(sB0, cur ^ 1, b0); }
                __syncthreads();
            }
        }

        // ---- Pass 3: A = h2(prev). Resident Whh2 -> aG2 ----
        {
            const half* hA = g_hst[2][rp];
            ldA(hA, 0, a0, a1);
            stA(0, a0, a1);
            __syncthreads();
            for (int ch = 0; ch < 16; ch++) {
                int cur = ch & 1;
                if (ch < 15) ldA(hA, (ch + 1) * 64, a0, a1);
#pragma unroll
                for (int ks = 0; ks < 4; ks++) {
                    wmma::fragment<wmma::matrix_a, 16, 16, 16, half, wmma::row_major> af;
                    wmma::fragment<wmma::matrix_b, 16, 16, 16, half, wmma::col_major> f1;
                    wmma::load_matrix_sync(af, &sA[cur * ABUF + (wm * 16) * SLD + ks * 16], SLD);
                    wmma::load_matrix_sync(f1, &sWres[1 * 32 * RLD + (wn * 16) * RLD + ch * 64 + ks * 16], RLD);
                    wmma::mma_sync(aG2, af, f1, aG2);
                }
                if (ch < 15) stA(cur ^ 1, a0, a1);
                __syncthreads();
            }
        }

        // ---- Cells: L0, L1, L2 (sg reused; sync-bracketed) ----
        const float* row = &sg[bq * 36];
        int hidx = nb * 8 + hh2;

        wmma::store_matrix_sync(&sg[(wm * 16) * 36 + wn * 16], aG0, 36, wmma::mem_row_major);
        __syncthreads();
        if (v0) {
            float iv0 = row[hh2] + x0.x + sbias[hh2],           iv1 = row[hh2 + 1] + x0.y + sbias[hh2 + 1];
            float fv0 = row[8 + hh2] + x1.x + sbias[8 + hh2],   fv1 = row[8 + hh2 + 1] + x1.y + sbias[8 + hh2 + 1];
            float gv0 = row[16 + hh2] + x2.x + sbias[16 + hh2], gv1 = row[16 + hh2 + 1] + x2.y + sbias[16 + hh2 + 1];
            float ov0 = row[24 + hh2] + x3.x + sbias[24 + hh2], ov1 = row[24 + hh2 + 1] + x3.y + sbias[24 + hh2 + 1];
            c0a = fsig(fv0) * c0a + fsig(iv0) * ftanh(gv0);
            c0b = fsig(fv1) * c0b + fsig(iv1) * ftanh(gv1);
            __half2 ph;
            ph.x = __float2half(fsig(ov0) * ftanh(c0a));
            ph.y = __float2half(fsig(ov1) * ftanh(c0b));
            *(__half2*)&g_hst[0][wp][bq * HHH + hidx] = ph;
        }
        __syncthreads();

        wmma::store_matrix_sync(&sg[(wm * 16) * 36 + wn * 16], aG1, 36, wmma::mem_row_major);
        __syncthreads();
        if (v1) {
            const float* bb = sbias + 32;
            float iv0 = row[hh2] + bb[hh2],           iv1 = row[hh2 + 1] + bb[hh2 + 1];
            float fv0 = row[8 + hh2] + bb[8 + hh2],   fv1 = row[8 + hh2 + 1] + bb[8 + hh2 + 1];
            float gv0 = row[16 + hh2] + bb[16 + hh2], gv1 = row[16 + hh2 + 1] + bb[16 + hh2 + 1];
            float ov0 = row[24 + hh2] + bb[24 + hh2], ov1 = row[24 + hh2 + 1] + bb[24 + hh2 + 1];
            c1a = fsig(fv0) * c1a + fsig(iv0) * ftanh(gv0);
            c1b = fsig(fv1) * c1b + fsig(iv1) * ftanh(gv1);
            __half2 ph;
            ph.x = __float2half(fsig(ov0) * ftanh(c1a));
            ph.y = __float2half(fsig(ov1) * ftanh(c1b));
            *(__half2*)&g_hst[1][wp][bq * HHH + hidx] = ph;
        }
        __syncthreads();

        wmma::store_matrix_sync(&sg[(wm * 16) * 36 + wn * 16], aG2, 36, wmma::mem_row_major);
        __syncthreads();
        if (v2) {
            const float* bb = sbias + 64;
            float iv0 = row[hh2] + bb[hh2],           iv1 = row[hh2 + 1] + bb[hh2 + 1];
            float fv0 = row[8 + hh2] + bb[8 + hh2],   fv1 = row[8 + hh2 + 1] + bb[8 + hh2 + 1];
            float gv0 = row[16 + hh2] + bb[16 + hh2], gv1 = row[16 + hh2 + 1] + bb[16 + hh2 + 1];
            float ov0 = row[24 + hh2] + bb[24 + hh2], ov1 = row[24 + hh2 + 1] + bb[24 + hh2 + 1];
            c2a = fsig(fv0) * c2a + fsig(iv0) * ftanh(gv0);
            c2b = fsig(fv1) * c2b + fsig(iv1) * ftanh(gv1);
            float h0v = fsig(ov0) * ftanh(c2a);
            float h1v = fsig(ov1) * ftanh(c2b);
            __half2 ph;
            ph.x = __float2half(h0v);
            ph.y = __float2half(h1v);
            *(__half2*)&g_hst[2][wp][bq * HHH + hidx] = ph;
            if (s == NSTEP - 1) {
                g_hlast[bq * HHH + hidx]     = h0v;
                g_hlast[bq * HHH + hidx + 1] = h1v;
            }
        }

        // ---- Grid barrier (skip after last step) ----
        if (s < NSTEP - 1) {
            __threadfence();
            __syncthreads();
            if (tid == 0) {
                atomicAdd(&g_bar, 1u);
                unsigned want = (unsigned)(s + 1) * NBLK;
                volatile unsigned* p = &g_bar;
                while (*p < want) { }
                __threadfence();
            }
            __syncthreads();
        }
    }
}

// ----------------------------------------------------------------------------
// Final FC: out[b] = hlast[b, :] . fc_w + fc_b   (D_OUT = 1)
// ----------------------------------------------------------------------------
__global__ void fc_kernel(const float* __restrict__ fw, const float* __restrict__ fb,
                          float* __restrict__ out) {
    int b = blockIdx.x, tid = threadIdx.x;
    __shared__ float red[256];
    const float* hrow = &g_hlast[b * HHH];
    float s = 0.f;
    for (int h = tid; h < HHH; h += 256) s += hrow[h] * fw[h];
    red[tid] = s;
    __syncthreads();
    for (int off = 128; off; off >>= 1) {
        if (tid < off) red[tid] += red[tid + off];
        __syncthreads();
    }
    if (tid == 0) out[b] = red[0] + fb[0];
}

// ----------------------------------------------------------------------------
// Launch (fused kernel at my launch index 3 -> ncu capture slot)
// ----------------------------------------------------------------------------
extern "C" void kernel_launch(void* const* d_in, const int* in_sizes, int n_in,
                              void* d_out, int out_size) {
    cudaFuncSetAttribute(fused_lstm_kernel, cudaFuncAttributeMaxDynamicSharedMemorySize,
                         SMEM_TOTAL);

    prep_all<<<86016, 256>>>(
        (const float*)d_in[1], (const float*)d_in[2],
        (const float*)d_in[5], (const float*)d_in[6],
        (const float*)d_in[9], (const float*)d_in[10]);
    prep_misc<<<256, 256>>>(
        (const float*)d_in[3], (const float*)d_in[4],
        (const float*)d_in[7], (const float*)d_in[8],
        (const float*)d_in[11], (const float*)d_in[12]);
    xg_gemm_kernel<<<dim3(GGG / 128, MTOT / 128), 256>>>((const float*)d_in[0]);
    fused_lstm_kernel<<<NBLK, NTHR, SMEM_TOTAL>>>();
    fc_kernel<<<BATCH, 256>>>((const float*)d_in[13], (const float*)d_in[14],
                              (float*)d_out);
}

// round 14
// speedup vs baseline: 1.2659x; 1.1021x over previous
#include <cuda_runtime.h>
#include <cuda_fp16.h>
#include <cuda_pipeline.h>
#include <mma.h>
#include <cstdint>

using namespace nvcuda;

#define BATCH 64
#define TT    256
#define HHH   1024
#define GGG   4096
#define MTOT  (BATCH*TT)   // 16384

#define NBLK  128
#define NTHR  256
#define GR    32           // gate rows (perm) per block
#define WLD   1032         // smem row stride (halfs), mult of 8

// smem: sW 32*1032*2=66048 | sA 64*1032*2=132096 | sg 64*36*4=9216 | sbias 128
#define SMEM_TOTAL (66048 + 132096 + 9216 + 128)   // 207488

// ----------------------------------------------------------------------------
// Device-global scratch (allocation-free)
// ----------------------------------------------------------------------------
__device__ __align__(16) half  g_wih[3][GGG*HHH];   // [0]: first GGG*256 used
__device__ __align__(16) half  g_whh[3][GGG*HHH];
__device__            float g_bias[3][GGG];
__device__ __align__(16) float g_xg[(size_t)MTOT*GGG];
__device__ __align__(16) half  g_in[(size_t)MTOT*HHH];   // layer input (for l=1,2 xg)
__device__ __align__(16) half  g_h[2][BATCH*HHH];        // double-buffered hidden
__device__            float g_hlast[BATCH*HHH];
__device__            unsigned g_bar;                    // monotonic barrier counter

__device__ __forceinline__ int perm_row(int cp) {
    int pb = cp >> 5, r = cp & 31;
    return (r >> 3) * HHH + pb * 8 + (r & 7);
}
__device__ __forceinline__ float fsig(float x)  { return 1.f / (1.f + __expf(-x)); }
__device__ __forceinline__ float ftanh(float x) { return 1.f - 2.f / (__expf(2.f * x) + 1.f); }

// ----------------------------------------------------------------------------
// Prep: all 6 weight matrices, one launch
// ----------------------------------------------------------------------------
__global__ void prep_all(const float* __restrict__ wih0, const float* __restrict__ whh0,
                         const float* __restrict__ wih1, const float* __restrict__ whh1,
                         const float* __restrict__ wih2, const float* __restrict__ whh2) {
    size_t idx = (size_t)blockIdx.x * blockDim.x + threadIdx.x;
    const size_t N0 = (size_t)GGG * 256, NB = (size_t)GGG * HHH;
    if (idx >= N0 + 5 * NB) return;
    if (idx < N0) {
        int rp = (int)(idx / 256), c = (int)(idx % 256);
        g_wih[0][idx] = __float2half(wih0[(size_t)perm_row(rp) * 256 + c]);
        return;
    }
    idx -= N0;
    int region = (int)(idx / NB);
    size_t j = idx % NB;
    int rp = (int)(j / HHH), c = (int)(j % HHH);
    size_t src = (size_t)perm_row(rp) * HHH + c;
    switch (region) {
        case 0: g_whh[0][j] = __float2half(whh0[src]); break;
        case 1: g_wih[1][j] = __float2half(wih1[src]); break;
        case 2: g_whh[1][j] = __float2half(whh1[src]); break;
        case 3: g_wih[2][j] = __float2half(wih2[src]); break;
        default: g_whh[2][j] = __float2half(whh2[src]); break;
    }
}

// Biases, h-state zero (both parities), barrier counter — one launch.
__global__ void prep_misc(const float* __restrict__ bi0, const float* __restrict__ bh0,
                          const float* __restrict__ bi1, const float* __restrict__ bh1,
                          const float* __restrict__ bi2, const float* __restrict__ bh2) {
    int i = blockIdx.x * blockDim.x + threadIdx.x;     // 65536 threads
    half z = __float2half(0.f);
    g_h[0][i] = z;
    g_h[1][i] = z;
    if (i < 3 * GGG) {
        int l = i >> 12, cp = i & (GGG - 1);
        int r = perm_row(cp);
        const float* bi = (l == 0) ? bi0 : (l == 1) ? bi1 : bi2;
        const float* bh = (l == 0) ? bh0 : (l == 1) ? bh1 : bh2;
        g_bias[l][cp] = bi[r] + bh[r];
    }
    if (i == 0) g_bar = 0u;
}

// ----------------------------------------------------------------------------
// xg GEMM: g_xg[M,4096] = A[M,K](fp16) @ Wih[4096,K]^T, fp32 accum.
// Block tile 128x128, 8 warps, warp tile 64x32, k-chunk 32, reg-staged DB.
// Layer 0 reads fp32 x directly and converts on the fly.
// ----------------------------------------------------------------------------
__global__ void __launch_bounds__(256) xg_gemm_kernel(int l, int K,
                                                      const float* __restrict__ xsrc) {
    __shared__ __align__(32) half sA[2][128][40], sB[2][128][40];
    int m0 = blockIdx.y * 128, n0 = blockIdx.x * 128;
    int tid = threadIdx.x, warp = tid >> 5;
    int wm = warp >> 2, wn = warp & 3;
    bool f32src = (l == 0);

    wmma::fragment<wmma::accumulator, 16, 16, 16, float> acc[4][2];
#pragma unroll
    for (int i = 0; i < 4; i++)
#pragma unroll
        for (int j = 0; j < 2; j++) wmma::fill_fragment(acc[i][j], 0.f);

    const half* B = g_wih[l];
    int r = tid >> 1, c16 = (tid & 1) * 16;
    uint4 ra[2], rb[2];

#define LOAD_A(k0)                                                             \
    do {                                                                       \
        if (f32src) {                                                          \
            const float* p = xsrc + (size_t)(m0 + r) * K + (k0) + c16;         \
            float4 f0 = *(const float4*)(p + 0);                               \
            float4 f1 = *(const float4*)(p + 4);                               \
            float4 f2 = *(const float4*)(p + 8);                               \
            float4 f3 = *(const float4*)(p + 12);                              \
            __half2 h0 = __floats2half2_rn(f0.x, f0.y);                        \
            __half2 h1 = __floats2half2_rn(f0.z, f0.w);                        \
            __half2 h2 = __floats2half2_rn(f1.x, f1.y);                        \
            __half2 h3 = __floats2half2_rn(f1.z, f1.w);                        \
            __half2 h4 = __floats2half2_rn(f2.x, f2.y);                        \
            __half2 h5 = __floats2half2_rn(f2.z, f2.w);                        \
            __half2 h6 = __floats2half2_rn(f3.x, f3.y);                        \
            __half2 h7 = __floats2half2_rn(f3.z, f3.w);                        \
            ra[0] = make_uint4(*(unsigned*)&h0, *(unsigned*)&h1,               \
                               *(unsigned*)&h2, *(unsigned*)&h3);              \
            ra[1] = make_uint4(*(unsigned*)&h4, *(unsigned*)&h5,               \
                               *(unsigned*)&h6, *(unsigned*)&h7);              \
        } else {                                                               \
            const half* p = g_in + (size_t)(m0 + r) * K + (k0) + c16;          \
            ra[0] = *(const uint4*)p;                                          \
            ra[1] = *(const uint4*)(p + 8);                                    \
        }                                                                      \
    } while (0)
#define LOAD_B(k0)                                                             \
    do {                                                                       \
        const half* p = B + (size_t)(n0 + r) * K + (k0) + c16;                 \
        rb[0] = *(const uint4*)p;                                              \
        rb[1] = *(const uint4*)(p + 8);                                        \
    } while (0)
#define STS(buf)                                                               \
    do {                                                                       \
        *(uint4*)&sA[buf][r][c16]     = ra[0];                                 \
        *(uint4*)&sA[buf][r][c16 + 8] = ra[1];                                 \
        *(uint4*)&sB[buf][r][c16]     = rb[0];                                 \
        *(uint4*)&sB[buf][r][c16 + 8] = rb[1];                                 \
    } while (0)

    int nch = K / 32;
    LOAD_A(0); LOAD_B(0);
    STS(0);
    __syncthreads();
    for (int ch = 0; ch < nch; ch++) {
        int cur = ch & 1;
        if (ch + 1 < nch) { LOAD_A((ch + 1) * 32); LOAD_B((ch + 1) * 32); }
#pragma unroll
        for (int ks = 0; ks < 2; ks++) {
            wmma::fragment<wmma::matrix_a, 16, 16, 16, half, wmma::row_major> af[4];
            wmma::fragment<wmma::matrix_b, 16, 16, 16, half, wmma::col_major> bf[2];
#pragma unroll
            for (int i = 0; i < 4; i++)
                wmma::load_matrix_sync(af[i], &sA[cur][wm * 64 + i * 16][ks * 16], 40);
#pragma unroll
            for (int j = 0; j < 2; j++)
                wmma::load_matrix_sync(bf[j], &sB[cur][wn * 32 + j * 16][ks * 16], 40);
#pragma unroll
            for (int i = 0; i < 4; i++)
#pragma unroll
                for (int j = 0; j < 2; j++)
                    wmma::mma_sync(acc[i][j], af[i], bf[j], acc[i][j]);
        }
        if (ch + 1 < nch) STS(cur ^ 1);
        __syncthreads();
    }
#undef LOAD_A
#undef LOAD_B
#undef STS
#pragma unroll
    for (int i = 0; i < 4; i++)
#pragma unroll
        for (int j = 0; j < 2; j++) {
            size_t row = (size_t)(m0 + wm * 64 + i * 16);
            int col = n0 + wn * 32 + j * 16;
            wmma::store_matrix_sync(&g_xg[row * GGG + col], acc[i][j], GGG,
                                    wmma::mem_row_major);
        }
}

// ----------------------------------------------------------------------------
// Persistent per-layer recurrence: 128 co-resident blocks, block nb owns
// perm gate rows [32nb,32nb+32) => h slice [8nb,8nb+8). Whh slice smem-resident.
// Per step: cp.async full-K A tile (1 sync), 64 uninterrupted k-steps,
// fused cell, release/acquire grid barrier. h zeroed at t=255 for next layer.
// ----------------------------------------------------------------------------
__global__ void __launch_bounds__(NTHR, 1) layer_kernel(int l) {
    extern __shared__ __align__(16) char raw[];
    half*  sW    = (half*)raw;              // [32][WLD]
    half*  sA    = sW + 32 * WLD;           // [64][WLD]
    float* sg    = (float*)(sA + 64 * WLD); // [64][36]
    float* sbias = sg + 64 * 36;            // [32]

    int nb = blockIdx.x;
    int tid = threadIdx.x, warp = tid >> 5;
    int wm = warp >> 1, wn = warp & 1;      // 4x2 warps over 64x32

    // Resident Whh slice (32 rows x 1024)
    {
        const half* Bw = &g_whh[l][(size_t)(nb * GR) * HHH];
        for (int i = tid; i < 32 * 128; i += NTHR) {
            int r = i >> 7, c = (i & 127) * 8;
            *(uint4*)&sW[r * WLD + c] = *(const uint4*)&Bw[(size_t)r * HHH + c];
        }
        if (tid < 32) sbias[tid] = g_bias[l][nb * GR + tid];
    }
    __syncthreads();

    int bq = tid >> 2, hh2 = (tid & 3) * 2;
    float c0 = 0.f, c1 = 0.f;
    unsigned bbase = (unsigned)l * 255u * NBLK;
    unsigned* gb = &g_bar;

    wmma::fragment<wmma::accumulator, 16, 16, 16, float> acc0, acc1;

    for (int t = 0; t < TT; t++) {
        int rp = t & 1, wp = rp ^ 1;
        const half* Ah = g_h[rp];

        // Async-fill full-K A tile: 64 rows x 1024 halfs = 8192 x 16B
#pragma unroll
        for (int u = 0; u < 32; u++) {
            int idx = tid + u * NTHR;
            int r = idx >> 7, c = (idx & 127) * 8;
            __pipeline_memcpy_async(&sA[r * WLD + c], &Ah[(size_t)r * HHH + c], 16);
        }
        __pipeline_commit();

        // xg prefetch (regular LDGs, overlap with cp.async drain)
        size_t xb = ((size_t)bq * TT + t) * GGG + nb * GR;
        float2 x0 = *(const float2*)&g_xg[xb + hh2];
        float2 x1 = *(const float2*)&g_xg[xb + 8 + hh2];
        float2 x2 = *(const float2*)&g_xg[xb + 16 + hh2];
        float2 x3 = *(const float2*)&g_xg[xb + 24 + hh2];

        wmma::fill_fragment(acc0, 0.f);
        wmma::fill_fragment(acc1, 0.f);

        __pipeline_wait_prior(0);
        __syncthreads();

        // 64 uninterrupted k-steps (dual accumulator chains)
#pragma unroll 8
        for (int ks = 0; ks < 64; ks++) {
            wmma::fragment<wmma::matrix_a, 16, 16, 16, half, wmma::row_major> af;
            wmma::fragment<wmma::matrix_b, 16, 16, 16, half, wmma::col_major> bf;
            wmma::load_matrix_sync(af, &sA[(wm * 16) * WLD + ks * 16], WLD);
            wmma::load_matrix_sync(bf, &sW[(wn * 16) * WLD + ks * 16], WLD);
            if (ks & 1) wmma::mma_sync(acc1, af, bf, acc1);
            else        wmma::mma_sync(acc0, af, bf, acc0);
        }
#pragma unroll
        for (int e = 0; e < acc0.num_elements; e++) acc0.x[e] += acc1.x[e];
        wmma::store_matrix_sync(&sg[(wm * 16) * 36 + wn * 16], acc0, 36,
                                wmma::mem_row_major);
        __syncthreads();

        // Fused LSTM cell (2 (b,h) pairs per thread)
        {
            const float* row = &sg[bq * 36];
            bool last = (t == TT - 1);
            float iv0 = row[hh2] + x0.x + sbias[hh2];
            float iv1 = row[hh2 + 1] + x0.y + sbias[hh2 + 1];
            float fv0 = row[8 + hh2] + x1.x + sbias[8 + hh2];
            float fv1 = row[8 + hh2 + 1] + x1.y + sbias[8 + hh2 + 1];
            float gv0 = row[16 + hh2] + x2.x + sbias[16 + hh2];
            float gv1 = row[16 + hh2 + 1] + x2.y + sbias[16 + hh2 + 1];
            float ov0 = row[24 + hh2] + x3.x + sbias[24 + hh2];
            float ov1 = row[24 + hh2 + 1] + x3.y + sbias[24 + hh2 + 1];

            c0 = fsig(fv0) * c0 + fsig(iv0) * ftanh(gv0);
            c1 = fsig(fv1) * c1 + fsig(iv1) * ftanh(gv1);
            float h0 = fsig(ov0) * ftanh(c0);
            float h1 = fsig(ov1) * ftanh(c1);

            int hidx = nb * 8 + hh2;
            __half2 ph, z2;
            ph.x = __float2half(h0); ph.y = __float2half(h1);
            z2.x = __float2half(0.f); z2.y = __float2half(0.f);
            // at t=255 write zeros so the next layer starts from h=0
            *(__half2*)&g_h[wp][bq * HHH + hidx] = last ? z2 : ph;
            if (l < 2) {
                size_t m = (size_t)bq * TT + t;
                *(__half2*)&g_in[m * HHH + hidx] = ph;
            }
            if (l == 2 && last) {
                g_hlast[bq * HHH + hidx]     = h0;
                g_hlast[bq * HHH + hidx + 1] = h1;
            }
        }

        // Release/acquire grid barrier (skip after last step)
        if (t < TT - 1) {
            __syncthreads();                    // all h-stores issued
            if (tid == 0) {
                asm volatile("red.release.gpu.global.add.u32 [%0], 1;"
                             :: "l"(gb) : "memory");
                unsigned want = bbase + (unsigned)(t + 1) * NBLK;
                unsigned v;
                do {
                    asm volatile("ld.acquire.gpu.global.u32 %0, [%1];"
                                 : "=r"(v) : "l"(gb) : "memory");
                } while (v < want);
            }
            __syncthreads();
        }
    }
}

// ----------------------------------------------------------------------------
// Final FC: out[b] = hlast[b, :] . fc_w + fc_b   (D_OUT = 1)
// ----------------------------------------------------------------------------
__global__ void fc_kernel(const float* __restrict__ fw, const float* __restrict__ fb,
                          float* __restrict__ out) {
    int b = blockIdx.x, tid = threadIdx.x;
    __shared__ float red[256];
    const float* hrow = &g_hlast[b * HHH];
    float s = 0.f;
    for (int h = tid; h < HHH; h += 256) s += hrow[h] * fw[h];
    red[tid] = s;
    __syncthreads();
    for (int off = 128; off; off >>= 1) {
        if (tid < off) red[tid] += red[tid + off];
        __syncthreads();
    }
    if (tid == 0) out[b] = red[0] + fb[0];
}

// ----------------------------------------------------------------------------
// Launch (layer_kernel(0) at my index 3 -> ncu capture slot)
// ----------------------------------------------------------------------------
extern "C" void kernel_launch(void* const* d_in, const int* in_sizes, int n_in,
                              void* d_out, int out_size) {
    const float* x = (const float*)d_in[0];

    cudaFuncSetAttribute(layer_kernel, cudaFuncAttributeMaxDynamicSharedMemorySize,
                         SMEM_TOTAL);

    prep_all<<<86016, 256>>>(
        (const float*)d_in[1], (const float*)d_in[2],
        (const float*)d_in[5], (const float*)d_in[6],
        (const float*)d_in[9], (const float*)d_in[10]);
    prep_misc<<<256, 256>>>(
        (const float*)d_in[3], (const float*)d_in[4],
        (const float*)d_in[7], (const float*)d_in[8],
        (const float*)d_in[11], (const float*)d_in[12]);

    for (int l = 0; l < 3; l++) {
        int K = (l == 0) ? 256 : 1024;
        xg_gemm_kernel<<<dim3(GGG / 128, MTOT / 128), 256>>>(l, K, x);
        layer_kernel<<<NBLK, NTHR, SMEM_TOTAL>>>(l);
    }
    fc_kernel<<<BATCH, 256>>>((const float*)d_in[13], (const float*)d_in[14],
                              (float*)d_out);
}

// round 15
// speedup vs baseline: 1.3767x; 1.0875x over previous
#include <cuda_runtime.h>
#include <cuda_fp16.h>
#include <cuda_pipeline.h>
#include <mma.h>
#include <cstdint>

using namespace nvcuda;

#define BATCH 64
#define TT    256
#define HHH   1024
#define GGG   4096
#define MTOT  (BATCH*TT)   // 16384

#define NBLK  128
#define NTHR  512          // 16 warps: two split-K groups of 8
#define GR    32           // gate rows (perm) per block
#define WLD   1032         // smem row stride (halfs), mult of 8

// smem: sW 32*1032*2=66048 | sA 64*1032*2=132096 | sg 2*64*36*4=18432 | sbias 128
#define SMEM_TOTAL (66048 + 132096 + 18432 + 128)   // 216704

// ----------------------------------------------------------------------------
// Device-global scratch (allocation-free)
// ----------------------------------------------------------------------------
__device__ __align__(16) half  g_wih[3][GGG*HHH];   // [0]: first GGG*256 used
__device__ __align__(16) half  g_whh[3][GGG*HHH];
__device__            float g_bias[3][GGG];
__device__ __align__(16) float g_xg[(size_t)MTOT*GGG];
__device__ __align__(16) half  g_in[(size_t)MTOT*HHH];   // layer input (for l=1,2 xg)
__device__ __align__(16) half  g_h[2][BATCH*HHH];        // double-buffered hidden
__device__            float g_hlast[BATCH*HHH];
__device__            unsigned g_bar;                    // monotonic barrier counter

__device__ __forceinline__ int perm_row(int cp) {
    int pb = cp >> 5, r = cp & 31;
    return (r >> 3) * HHH + pb * 8 + (r & 7);
}
__device__ __forceinline__ float fsig(float x)  { return 1.f / (1.f + __expf(-x)); }
__device__ __forceinline__ float ftanh(float x) { return 1.f - 2.f / (__expf(2.f * x) + 1.f); }

// ----------------------------------------------------------------------------
// Prep: all 6 weight matrices, one launch
// ----------------------------------------------------------------------------
__global__ void prep_all(const float* __restrict__ wih0, const float* __restrict__ whh0,
                         const float* __restrict__ wih1, const float* __restrict__ whh1,
                         const float* __restrict__ wih2, const float* __restrict__ whh2) {
    size_t idx = (size_t)blockIdx.x * blockDim.x + threadIdx.x;
    const size_t N0 = (size_t)GGG * 256, NB = (size_t)GGG * HHH;
    if (idx >= N0 + 5 * NB) return;
    if (idx < N0) {
        int rp = (int)(idx / 256), c = (int)(idx % 256);
        g_wih[0][idx] = __float2half(wih0[(size_t)perm_row(rp) * 256 + c]);
        return;
    }
    idx -= N0;
    int region = (int)(idx / NB);
    size_t j = idx % NB;
    int rp = (int)(j / HHH), c = (int)(j % HHH);
    size_t src = (size_t)perm_row(rp) * HHH + c;
    switch (region) {
        case 0: g_whh[0][j] = __float2half(whh0[src]); break;
        case 1: g_wih[1][j] = __float2half(wih1[src]); break;
        case 2: g_whh[1][j] = __float2half(whh1[src]); break;
        case 3: g_wih[2][j] = __float2half(wih2[src]); break;
        default: g_whh[2][j] = __float2half(whh2[src]); break;
    }
}

// Biases, h-state zero (both parities), barrier counter — one launch.
__global__ void prep_misc(const float* __restrict__ bi0, const float* __restrict__ bh0,
                          const float* __restrict__ bi1, const float* __restrict__ bh1,
                          const float* __restrict__ bi2, const float* __restrict__ bh2) {
    int i = blockIdx.x * blockDim.x + threadIdx.x;     // 65536 threads
    half z = __float2half(0.f);
    g_h[0][i] = z;
    g_h[1][i] = z;
    if (i < 3 * GGG) {
        int l = i >> 12, cp = i & (GGG - 1);
        int r = perm_row(cp);
        const float* bi = (l == 0) ? bi0 : (l == 1) ? bi1 : bi2;
        const float* bh = (l == 0) ? bh0 : (l == 1) ? bh1 : bh2;
        g_bias[l][cp] = bi[r] + bh[r];
    }
    if (i == 0) g_bar = 0u;
}

// ----------------------------------------------------------------------------
// xg GEMM: g_xg[M,4096] = A[M,K](fp16) @ Wih[4096,K]^T, fp32 accum.
// Block tile 128x128, 8 warps, warp tile 64x32, k-chunk 32, reg-staged DB.
// Layer 0 reads fp32 x directly and converts on the fly.
// ----------------------------------------------------------------------------
__global__ void __launch_bounds__(256) xg_gemm_kernel(int l, int K,
                                                      const float* __restrict__ xsrc) {
    __shared__ __align__(32) half sA[2][128][40], sB[2][128][40];
    int m0 = blockIdx.y * 128, n0 = blockIdx.x * 128;
    int tid = threadIdx.x, warp = tid >> 5;
    int wm = warp >> 2, wn = warp & 3;
    bool f32src = (l == 0);

    wmma::fragment<wmma::accumulator, 16, 16, 16, float> acc[4][2];
#pragma unroll
    for (int i = 0; i < 4; i++)
#pragma unroll
        for (int j = 0; j < 2; j++) wmma::fill_fragment(acc[i][j], 0.f);

    const half* B = g_wih[l];
    int r = tid >> 1, c16 = (tid & 1) * 16;
    uint4 ra[2], rb[2];

#define LOAD_A(k0)                                                             \
    do {                                                                       \
        if (f32src) {                                                          \
            const float* p = xsrc + (size_t)(m0 + r) * K + (k0) + c16;         \
            float4 f0 = *(const float4*)(p + 0);                               \
            float4 f1 = *(const float4*)(p + 4);                               \
            float4 f2 = *(const float4*)(p + 8);                               \
            float4 f3 = *(const float4*)(p + 12);                              \
            __half2 h0 = __floats2half2_rn(f0.x, f0.y);                        \
            __half2 h1 = __floats2half2_rn(f0.z, f0.w);                        \
            __half2 h2 = __floats2half2_rn(f1.x, f1.y);                        \
            __half2 h3 = __floats2half2_rn(f1.z, f1.w);                        \
            __half2 h4 = __floats2half2_rn(f2.x, f2.y);                        \
            __half2 h5 = __floats2half2_rn(f2.z, f2.w);                        \
            __half2 h6 = __floats2half2_rn(f3.x, f3.y);                        \
            __half2 h7 = __floats2half2_rn(f3.z, f3.w);                        \
            ra[0] = make_uint4(*(unsigned*)&h0, *(unsigned*)&h1,               \
                               *(unsigned*)&h2, *(unsigned*)&h3);              \
            ra[1] = make_uint4(*(unsigned*)&h4, *(unsigned*)&h5,               \
                               *(unsigned*)&h6, *(unsigned*)&h7);              \
        } else {                                                               \
            const half* p = g_in + (size_t)(m0 + r) * K + (k0) + c16;          \
            ra[0] = *(const uint4*)p;                                          \
            ra[1] = *(const uint4*)(p + 8);                                    \
        }                                                                      \
    } while (0)
#define LOAD_B(k0)                                                             \
    do {                                                                       \
        const half* p = B + (size_t)(n0 + r) * K + (k0) + c16;                 \
        rb[0] = *(const uint4*)p;                                              \
        rb[1] = *(const uint4*)(p + 8);                                        \
    } while (0)
#define STS(buf)                                                               \
    do {                                                                       \
        *(uint4*)&sA[buf][r][c16]     = ra[0];                                 \
        *(uint4*)&sA[buf][r][c16 + 8] = ra[1];                                 \
        *(uint4*)&sB[buf][r][c16]     = rb[0];                                 \
        *(uint4*)&sB[buf][r][c16 + 8] = rb[1];                                 \
    } while (0)

    int nch = K / 32;
    LOAD_A(0); LOAD_B(0);
    STS(0);
    __syncthreads();
    for (int ch = 0; ch < nch; ch++) {
        int cur = ch & 1;
        if (ch + 1 < nch) { LOAD_A((ch + 1) * 32); LOAD_B((ch + 1) * 32); }
#pragma unroll
        for (int ks = 0; ks < 2; ks++) {
            wmma::fragment<wmma::matrix_a, 16, 16, 16, half, wmma::row_major> af[4];
            wmma::fragment<wmma::matrix_b, 16, 16, 16, half, wmma::col_major> bf[2];
#pragma unroll
            for (int i = 0; i < 4; i++)
                wmma::load_matrix_sync(af[i], &sA[cur][wm * 64 + i * 16][ks * 16], 40);
#pragma unroll
            for (int j = 0; j < 2; j++)
                wmma::load_matrix_sync(bf[j], &sB[cur][wn * 32 + j * 16][ks * 16], 40);
#pragma unroll
            for (int i = 0; i < 4; i++)
#pragma unroll
                for (int j = 0; j < 2; j++)
                    wmma::mma_sync(acc[i][j], af[i], bf[j], acc[i][j]);
        }
        if (ch + 1 < nch) STS(cur ^ 1);
        __syncthreads();
    }
#undef LOAD_A
#undef LOAD_B
#undef STS
#pragma unroll
    for (int i = 0; i < 4; i++)
#pragma unroll
        for (int j = 0; j < 2; j++) {
            size_t row = (size_t)(m0 + wm * 64 + i * 16);
            int col = n0 + wn * 32 + j * 16;
            wmma::store_matrix_sync(&g_xg[row * GGG + col], acc[i][j], GGG,
                                    wmma::mem_row_major);
        }
}

// ----------------------------------------------------------------------------
// Persistent per-layer recurrence: 128 co-resident blocks x 512 threads.
// Block nb owns perm gate rows [32nb,32nb+32) => h slice [8nb,8nb+8).
// 16 warps = 2 split-K groups (K halves); each group fills its own A half
// (cp.async) and syncs on a PRIVATE named barrier -> decoupled fill/MMA.
// Whh slice smem-resident. Fused cell; release/acquire grid barrier.
// ----------------------------------------------------------------------------
__global__ void __launch_bounds__(NTHR, 1) layer_kernel(int l) {
    extern __shared__ __align__(16) char raw[];
    half*  sW    = (half*)raw;              // [32][WLD]
    half*  sA    = sW + 32 * WLD;           // [64][WLD]
    float* sg    = (float*)(sA + 64 * WLD); // [2][64][36]
    float* sbias = sg + 2 * 64 * 36;        // [32]

    int nb = blockIdx.x;
    int tid = threadIdx.x, warp = tid >> 5;
    int wk = warp >> 3;                     // split-K group 0/1
    int w8 = warp & 7;
    int wm = w8 >> 1, wn = w8 & 1;          // 4x2 warps over 64x32 tile
    int gtid = tid & 255;                   // id within group
    int kofs = wk * 512;

    // Resident Whh slice (32 rows x 1024)
    {
        const half* Bw = &g_whh[l][(size_t)(nb * GR) * HHH];
        for (int i = tid; i < 32 * 128; i += NTHR) {
            int r = i >> 7, c = (i & 127) * 8;
            *(uint4*)&sW[r * WLD + c] = *(const uint4*)&Bw[(size_t)r * HHH + c];
        }
        if (tid < 32) sbias[tid] = g_bias[l][nb * GR + tid];
    }
    __syncthreads();

    int bq = tid >> 3, hh = tid & 7;        // one (b,h) pair per thread
    float cst = 0.f;
    unsigned bbase = (unsigned)l * 255u * NBLK;
    unsigned* gb = &g_bar;

    wmma::fragment<wmma::accumulator, 16, 16, 16, float> acc0, acc1;

    for (int t = 0; t < TT; t++) {
        int rp = t & 1, wp = rp ^ 1;
        const half* Ah = g_h[rp];

        // Group-private async fill of own A half: 64 rows x 512 halfs = 4096x16B
#pragma unroll
        for (int u = 0; u < 16; u++) {
            int idx = gtid + u * 256;                 // 0..4095
            int r = idx >> 6, c = (idx & 63) * 8 + kofs;
            __pipeline_memcpy_async(&sA[r * WLD + c], &Ah[(size_t)r * HHH + c], 16);
        }
        __pipeline_commit();

        // xg prefetch (4 scalars; overlaps cp.async drain)
        size_t xb = ((size_t)bq * TT + t) * GGG + nb * GR + hh;
        float xi = g_xg[xb], xf = g_xg[xb + 8], xgg = g_xg[xb + 16], xo = g_xg[xb + 24];

        wmma::fill_fragment(acc0, 0.f);
        wmma::fill_fragment(acc1, 0.f);

        __pipeline_wait_prior(0);
        asm volatile("bar.sync %0, 256;" :: "r"(1 + wk) : "memory");

        // 32 k-steps over own K half (dual accumulator chains)
#pragma unroll 8
        for (int ks = 0; ks < 32; ks++) {
            wmma::fragment<wmma::matrix_a, 16, 16, 16, half, wmma::row_major> af;
            wmma::fragment<wmma::matrix_b, 16, 16, 16, half, wmma::col_major> bf;
            wmma::load_matrix_sync(af, &sA[(wm * 16) * WLD + kofs + ks * 16], WLD);
            wmma::load_matrix_sync(bf, &sW[(wn * 16) * WLD + kofs + ks * 16], WLD);
            if (ks & 1) wmma::mma_sync(acc1, af, bf, acc1);
            else        wmma::mma_sync(acc0, af, bf, acc0);
        }
#pragma unroll
        for (int e = 0; e < acc0.num_elements; e++) acc0.x[e] += acc1.x[e];
        wmma::store_matrix_sync(&sg[wk * 64 * 36 + (wm * 16) * 36 + wn * 16], acc0,
                                36, wmma::mem_row_major);
        __syncthreads();

        // Fused LSTM cell: one (b,h) pair per thread; fold split-K partials
        {
            const float* r0 = &sg[bq * 36];
            const float* r1 = &sg[64 * 36 + bq * 36];
            bool last = (t == TT - 1);
            float iv = r0[hh]      + r1[hh]      + xi  + sbias[hh];
            float fv = r0[8 + hh]  + r1[8 + hh]  + xf  + sbias[8 + hh];
            float gv = r0[16 + hh] + r1[16 + hh] + xgg + sbias[16 + hh];
            float ov = r0[24 + hh] + r1[24 + hh] + xo  + sbias[24 + hh];

            cst = fsig(fv) * cst + fsig(iv) * ftanh(gv);
            float hv = fsig(ov) * ftanh(cst);

            int hidx = nb * 8 + hh;
            half ph = __float2half(hv);
            half zz = __float2half(0.f);
            // at t=255 write zeros so the next layer starts from h=0
            g_h[wp][bq * HHH + hidx] = last ? zz : ph;
            if (l < 2) {
                size_t m = (size_t)bq * TT + t;
                g_in[m * HHH + hidx] = ph;
            }
            if (l == 2 && last) g_hlast[bq * HHH + hidx] = hv;
        }

        // Release/acquire grid barrier (skip after last step)
        if (t < TT - 1) {
            __syncthreads();                    // all h-stores issued
            if (tid == 0) {
                asm volatile("red.release.gpu.global.add.u32 [%0], 1;"
                             :: "l"(gb) : "memory");
                unsigned want = bbase + (unsigned)(t + 1) * NBLK;
                unsigned v;
                do {
                    asm volatile("ld.acquire.gpu.global.u32 %0, [%1];"
                                 : "=r"(v) : "l"(gb) : "memory");
                } while (v < want);
            }
            __syncthreads();
        }
    }
}

// ----------------------------------------------------------------------------
// Final FC: out[b] = hlast[b, :] . fc_w + fc_b   (D_OUT = 1)
// ----------------------------------------------------------------------------
__global__ void fc_kernel(const float* __restrict__ fw, const float* __restrict__ fb,
                          float* __restrict__ out) {
    int b = blockIdx.x, tid = threadIdx.x;
    __shared__ float red[256];
    const float* hrow = &g_hlast[b * HHH];
    float s = 0.f;
    for (int h = tid; h < HHH; h += 256) s += hrow[h] * fw[h];
    red[tid] = s;
    __syncthreads();
    for (int off = 128; off; off >>= 1) {
        if (tid < off) red[tid] += red[tid + off];
        __syncthreads();
    }
    if (tid == 0) out[b] = red[0] + fb[0];
}

// ----------------------------------------------------------------------------
// Launch (layer_kernel(0) at my index 3 -> ncu capture slot)
// ----------------------------------------------------------------------------
extern "C" void kernel_launch(void* const* d_in, const int* in_sizes, int n_in,
                              void* d_out, int out_size) {
    const float* x = (const float*)d_in[0];

    cudaFuncSetAttribute(layer_kernel, cudaFuncAttributeMaxDynamicSharedMemorySize,
                         SMEM_TOTAL);

    prep_all<<<86016, 256>>>(
        (const float*)d_in[1], (const float*)d_in[2],
        (const float*)d_in[5], (const float*)d_in[6],
        (const float*)d_in[9], (const float*)d_in[10]);
    prep_misc<<<256, 256>>>(
        (const float*)d_in[3], (const float*)d_in[4],
        (const float*)d_in[7], (const float*)d_in[8],
        (const float*)d_in[11], (const float*)d_in[12]);

    for (int l = 0; l < 3; l++) {
        int K = (l == 0) ? 256 : 1024;
        xg_gemm_kernel<<<dim3(GGG / 128, MTOT / 128), 256>>>(l, K, x);
        layer_kernel<<<NBLK, NTHR, SMEM_TOTAL>>>(l);
    }
    fc_kernel<<<BATCH, 256>>>((const float*)d_in[13], (const float*)d_in[14],
                              (float*)d_out);
}